// round 4
// baseline (speedup 1.0000x reference)
#include <cuda_runtime.h>

// Network24: tiny 2->2->1 synapse MLP, pointwise over B rows. 12 B/row HBM.
// R4: single launch; vectorized param loads (hoisted, L1-hit); 16 rows/thread;
//     packed f32x2 FMA math (Blackwell FFMA2 via PTX); MUFU.TANH sigmoid.

typedef unsigned long long u64;

__device__ __forceinline__ u64 pk(float lo, float hi) {
    u64 r; asm("mov.b64 %0, {%1, %2};" : "=l"(r) : "f"(lo), "f"(hi)); return r;
}
__device__ __forceinline__ void upk(float& lo, float& hi, u64 v) {
    asm("mov.b64 {%0, %1}, %2;" : "=f"(lo), "=f"(hi) : "l"(v));
}
__device__ __forceinline__ u64 fma2(u64 a, u64 b, u64 c) {
    u64 r; asm("fma.rn.f32x2 %0, %1, %2, %3;" : "=l"(r) : "l"(a), "l"(b), "l"(c)); return r;
}
__device__ __forceinline__ u64 mul2(u64 a, u64 b) {
    u64 r; asm("mul.rn.f32x2 %0, %1, %2;" : "=l"(r) : "l"(a), "l"(b)); return r;
}
__device__ __forceinline__ u64 add2(u64 a, u64 b) {
    u64 r; asm("add.rn.f32x2 %0, %1, %2;" : "=l"(r) : "l"(a), "l"(b)); return r;
}

__device__ __forceinline__ float tanh_ap(float z) {
    float t; asm("tanh.approx.f32 %0, %1;" : "=f"(t) : "f"(z)); return t;
}

// packed sigmoid: sigmoid(z) = 0.5*tanh(0.5*z) + 0.5
__device__ __forceinline__ u64 sig2(u64 z, u64 HALF) {
    u64 zh = mul2(HALF, z);
    float z0, z1; upk(z0, z1, zh);
    return fma2(HALF, pk(tanh_ap(z0), tanh_ap(z1)), HALF);
}

// packed pow: powers are grid-uniform; p==1 branch is warp-uniform (dataset: p=1)
__device__ __forceinline__ u64 pow2p(u64 x, float p) {
    if (p == 1.0f) return x;
    float a, b; upk(a, b, x);
    return pk(__powf(a, p), __powf(b, p));
}

struct PP {
    u64 W00, W01, W10, W11, B0, B1;   // fc1 weights/bias (broadcast pairs)
    u64 M0, M1, M2, M3, BIAS3, HALF;  // m4 weights/bias
    float p00, p01, p10, p11;         // fc1_power
    float q0, q1, q2, q3;             // m4_power
};

// two rows packed: X0={x0 rowA, x0 rowB}, X1={x1 rowA, x1 rowB}
__device__ __forceinline__ u64 rows2(u64 X0, u64 X1, const PP& P) {
    u64 h0 = fma2(P.W00, pow2p(X0, P.p00), fma2(P.W01, pow2p(X1, P.p01), P.B0));
    u64 h1 = fma2(P.W10, pow2p(X0, P.p10), fma2(P.W11, pow2p(X1, P.p11), P.B1));
    h0 = sig2(h0, P.HALF);
    h1 = sig2(h1, P.HALF);
    u64 s  = mul2(P.M0, pow2p(h0, P.q0));
    s      = fma2(P.M1, pow2p(h1, P.q1), s);
    s      = add2(s, P.BIAS3);
    u64 p1 = mul2(P.M2, pow2p(h0, P.q2));
    u64 p2 = mul2(P.M3, pow2p(h1, P.q3));
    return sig2(fma2(p1, p2, s), P.HALF);
}

// one float4 = rows (x0a,x1a,x0b,x1b) -> packed result for 2 rows
__device__ __forceinline__ u64 quad(float4 v, const PP& P) {
    return rows2(pk(v.x, v.z), pk(v.y, v.w), P);
}

__device__ __forceinline__ PP load_pp(const float* __restrict__ fc1_tw,
                                      const float* __restrict__ fc1_power,
                                      const float* __restrict__ fc1_bias,
                                      const float* __restrict__ m4_tw,
                                      const float* __restrict__ m4_power,
                                      const float* __restrict__ m4_bias3) {
    PP P;
    // fc1_tw (2,2,3): need idx 0,3,6,9 -> three float4 loads
    float4 t0 = __ldg((const float4*)(fc1_tw + 0));
    float4 t1 = __ldg((const float4*)(fc1_tw + 4));
    float4 t2 = __ldg((const float4*)(fc1_tw + 8));
    P.W00 = pk(t0.x, t0.x); P.W01 = pk(t0.w, t0.w);
    P.W10 = pk(t1.z, t1.z); P.W11 = pk(t2.y, t2.y);
    float4 fp = __ldg((const float4*)fc1_power);
    P.p00 = fp.x; P.p01 = fp.y; P.p10 = fp.z; P.p11 = fp.w;
    float2 fb = __ldg((const float2*)fc1_bias);
    P.B0 = pk(fb.x, fb.x); P.B1 = pk(fb.y, fb.y);
    // m4_tw (4,3): need idx 0,3,6,9
    float4 m0 = __ldg((const float4*)(m4_tw + 0));
    float4 m1 = __ldg((const float4*)(m4_tw + 4));
    float4 m2 = __ldg((const float4*)(m4_tw + 8));
    P.M0 = pk(m0.x, m0.x); P.M1 = pk(m0.w, m0.w);
    P.M2 = pk(m1.z, m1.z); P.M3 = pk(m2.y, m2.y);
    float4 mq = __ldg((const float4*)m4_power);
    P.q0 = mq.x; P.q1 = mq.y; P.q2 = mq.z; P.q3 = mq.w;
    float b3 = __ldg(m4_bias3);
    P.BIAS3 = pk(b3, b3);
    P.HALF  = pk(0.5f, 0.5f);
    return P;
}

__global__ void __launch_bounds__(256)
net24_vec16_kernel(const float4* __restrict__ x4,   // 8 float4 = 16 rows
                   float4* __restrict__ out4,
                   const float* __restrict__ fc1_tw,
                   const float* __restrict__ fc1_power,
                   const float* __restrict__ fc1_bias,
                   const float* __restrict__ m4_tw,
                   const float* __restrict__ m4_power,
                   const float* __restrict__ m4_bias3,
                   int n16)                          // number of 16-row groups
{
    int i = blockIdx.x * blockDim.x + threadIdx.x;
    if (i >= n16) return;

    PP P = load_pp(fc1_tw, fc1_power, fc1_bias, m4_tw, m4_power, m4_bias3);

    const float4* src = x4 + 8 * i;
    float4* dst = out4 + 4 * i;

    // first half: rows 0..7
    float4 a0 = __ldcs(src + 0);
    float4 a1 = __ldcs(src + 1);
    float4 a2 = __ldcs(src + 2);
    float4 a3 = __ldcs(src + 3);
    float4 r0, r1;
    u64 q0 = quad(a0, P), q1 = quad(a1, P), q2 = quad(a2, P), q3 = quad(a3, P);
    upk(r0.x, r0.y, q0); upk(r0.z, r0.w, q1);
    upk(r1.x, r1.y, q2); upk(r1.z, r1.w, q3);
    __stcs(dst + 0, r0);
    __stcs(dst + 1, r1);

    // second half: rows 8..15
    float4 b0 = __ldcs(src + 4);
    float4 b1 = __ldcs(src + 5);
    float4 b2 = __ldcs(src + 6);
    float4 b3 = __ldcs(src + 7);
    float4 r2, r3;
    u64 q4 = quad(b0, P), q5 = quad(b1, P), q6 = quad(b2, P), q7 = quad(b3, P);
    upk(r2.x, r2.y, q4); upk(r2.z, r2.w, q5);
    upk(r3.x, r3.y, q6); upk(r3.z, r3.w, q7);
    __stcs(dst + 2, r2);
    __stcs(dst + 3, r3);
}

// scalar tail for B % 16 != 0 (not hit for B = 8388608)
__global__ void net24_tail_kernel(const float2* __restrict__ x2,
                                  float* __restrict__ out,
                                  const float* __restrict__ fc1_tw,
                                  const float* __restrict__ fc1_power,
                                  const float* __restrict__ fc1_bias,
                                  const float* __restrict__ m4_tw,
                                  const float* __restrict__ m4_power,
                                  const float* __restrict__ m4_bias3,
                                  int start, int n)
{
    int i = start + blockIdx.x * blockDim.x + threadIdx.x;
    if (i >= n) return;
    PP P = load_pp(fc1_tw, fc1_power, fc1_bias, m4_tw, m4_power, m4_bias3);
    float2 v = x2[i];
    u64 r = rows2(pk(v.x, v.x), pk(v.y, v.y), P);
    float lo, hi; upk(lo, hi, r);
    out[i] = lo;
}

extern "C" void kernel_launch(void* const* d_in, const int* in_sizes, int n_in,
                              void* d_out, int out_size)
{
    const float* x         = (const float*)d_in[0];
    const float* fc1_tw    = (const float*)d_in[1];
    const float* fc1_power = (const float*)d_in[2];
    const float* fc1_bias  = (const float*)d_in[3];
    const float* m4_tw     = (const float*)d_in[4];
    const float* m4_power  = (const float*)d_in[5];
    const float* m4_bias3  = (const float*)d_in[6];
    float* out = (float*)d_out;

    int B   = in_sizes[0] / 2;   // rows
    int n16 = B / 16;
    int rem_start = n16 * 16;

    if (n16 > 0) {
        int threads = 256;
        int blocks  = (n16 + threads - 1) / threads;
        net24_vec16_kernel<<<blocks, threads>>>(
            (const float4*)x, (float4*)out,
            fc1_tw, fc1_power, fc1_bias, m4_tw, m4_power, m4_bias3, n16);
    }
    if (rem_start < B) {
        int rem = B - rem_start;
        net24_tail_kernel<<<(rem + 127) / 128, 128>>>(
            (const float2*)x, out,
            fc1_tw, fc1_power, fc1_bias, m4_tw, m4_power, m4_bias3,
            rem_start, B);
    }
}

// round 6
// speedup vs baseline: 1.1778x; 1.1778x over previous
#include <cuda_runtime.h>

// Network24: tiny 2->2->1 synapse MLP, pointwise over B rows. 12 B/row HBM.
// R5: ONE kernel node. Params broadcast via shared memory (19 parallel LDGs
//     by the first warp of each block), 8 rows/thread, scalar FFMA math,
//     MUFU-class tanh sigmoid. Plain loads for x (L2-retain), streaming
//     stores for out.

__device__ __forceinline__ float fpow(float x, float p) {
    // powers are grid-uniform scalars; p==1 branch is warp-uniform
    return (p == 1.0f) ? x : __powf(x, p);
}

__device__ __forceinline__ float fsig(float z) {
    // sigmoid(z) = 0.5*tanh(z/2) + 0.5  -- single HW tanh
    float t;
    asm("tanh.approx.f32 %0, %1;" : "=f"(t) : "f"(0.5f * z));
    return fmaf(0.5f, t, 0.5f);
}

struct Params {
    float w00, w01, w10, w11;   // fc1_tw[i][j][0]
    float p00, p01, p10, p11;   // fc1_power[i][j]
    float b0, b1;               // fc1_bias
    float m0, m1, m2, m3;       // m4_tw[k][0]
    float q0, q1, q2, q3;       // m4_power
    float bias3;
};

__device__ __forceinline__ float net_row(float x0, float x1, const Params& P) {
    float h0 = fsig(fmaf(P.w00, fpow(x0, P.p00), fmaf(P.w01, fpow(x1, P.p01), P.b0)));
    float h1 = fsig(fmaf(P.w10, fpow(x0, P.p10), fmaf(P.w11, fpow(x1, P.p11), P.b1)));
    float s1 = P.m0 * fpow(h0, P.q0);
    float s2 = P.m1 * fpow(h1, P.q1);
    float p1 = P.m2 * fpow(h0, P.q2);
    float p2 = P.m3 * fpow(h1, P.q3);
    return fsig(fmaf(p1, p2, s1 + s2) + P.bias3);
}

// Gather one param scalar per lane (lanes 0..18).
__device__ __forceinline__ float gather_param(int t,
                                              const float* __restrict__ fc1_tw,
                                              const float* __restrict__ fc1_power,
                                              const float* __restrict__ fc1_bias,
                                              const float* __restrict__ m4_tw,
                                              const float* __restrict__ m4_power,
                                              const float* __restrict__ m4_bias3) {
    if (t < 4)  return fc1_tw[3 * t];         // w00 w01 w10 w11 (2,2,3)[i][j][0]
    if (t < 8)  return fc1_power[t - 4];      // p00 p01 p10 p11
    if (t < 10) return fc1_bias[t - 8];       // b0 b1
    if (t < 14) return m4_tw[3 * (t - 10)];   // m0 m1 m2 m3 (4,3)[k][0]
    if (t < 18) return m4_power[t - 14];      // q0 q1 q2 q3
    return m4_bias3[0];                       // bias3
}

__device__ __forceinline__ Params params_from_smem(const float* s) {
    Params P;
    P.w00 = s[0];  P.w01 = s[1];  P.w10 = s[2];  P.w11 = s[3];
    P.p00 = s[4];  P.p01 = s[5];  P.p10 = s[6];  P.p11 = s[7];
    P.b0  = s[8];  P.b1  = s[9];
    P.m0  = s[10]; P.m1  = s[11]; P.m2  = s[12]; P.m3  = s[13];
    P.q0  = s[14]; P.q1  = s[15]; P.q2  = s[16]; P.q3  = s[17];
    P.bias3 = s[18];
    return P;
}

__global__ void __launch_bounds__(256)
net24_vec8_kernel(const float4* __restrict__ x4,   // 4 float4 = 8 rows
                  float4* __restrict__ out4,
                  const float* __restrict__ fc1_tw,
                  const float* __restrict__ fc1_power,
                  const float* __restrict__ fc1_bias,
                  const float* __restrict__ m4_tw,
                  const float* __restrict__ m4_power,
                  const float* __restrict__ m4_bias3,
                  int n8)                            // number of 8-row groups
{
    __shared__ float sP[20];
    if (threadIdx.x < 19) {
        sP[threadIdx.x] = gather_param(threadIdx.x, fc1_tw, fc1_power, fc1_bias,
                                       m4_tw, m4_power, m4_bias3);
    }
    __syncthreads();

    int i = blockIdx.x * blockDim.x + threadIdx.x;
    if (i >= n8) return;

    // Rows 8i..8i+7 (x is [B,2] row-major). Plain loads -> L2-retained.
    float4 a = x4[4 * i + 0];
    float4 b = x4[4 * i + 1];
    float4 c = x4[4 * i + 2];
    float4 d = x4[4 * i + 3];

    Params P = params_from_smem(sP);

    float4 r0, r1;
    r0.x = net_row(a.x, a.y, P);
    r0.y = net_row(a.z, a.w, P);
    r0.z = net_row(b.x, b.y, P);
    r0.w = net_row(b.z, b.w, P);
    r1.x = net_row(c.x, c.y, P);
    r1.y = net_row(c.z, c.w, P);
    r1.z = net_row(d.x, d.y, P);
    r1.w = net_row(d.z, d.w, P);

    // Streaming stores: out is write-once, keep it out of L2 so x stays.
    __stcs(out4 + 2 * i + 0, r0);
    __stcs(out4 + 2 * i + 1, r1);
}

// scalar tail for B % 8 != 0 (not hit for B = 8388608)
__global__ void net24_tail_kernel(const float2* __restrict__ x2,
                                  float* __restrict__ out,
                                  const float* __restrict__ fc1_tw,
                                  const float* __restrict__ fc1_power,
                                  const float* __restrict__ fc1_bias,
                                  const float* __restrict__ m4_tw,
                                  const float* __restrict__ m4_power,
                                  const float* __restrict__ m4_bias3,
                                  int start, int n)
{
    __shared__ float sP[20];
    if (threadIdx.x < 19) {
        sP[threadIdx.x] = gather_param(threadIdx.x, fc1_tw, fc1_power, fc1_bias,
                                       m4_tw, m4_power, m4_bias3);
    }
    __syncthreads();

    int i = start + blockIdx.x * blockDim.x + threadIdx.x;
    if (i >= n) return;
    Params P = params_from_smem(sP);
    float2 v = x2[i];
    out[i] = net_row(v.x, v.y, P);
}

extern "C" void kernel_launch(void* const* d_in, const int* in_sizes, int n_in,
                              void* d_out, int out_size)
{
    const float* x         = (const float*)d_in[0];
    const float* fc1_tw    = (const float*)d_in[1];
    const float* fc1_power = (const float*)d_in[2];
    const float* fc1_bias  = (const float*)d_in[3];
    const float* m4_tw     = (const float*)d_in[4];
    const float* m4_power  = (const float*)d_in[5];
    const float* m4_bias3  = (const float*)d_in[6];
    float* out = (float*)d_out;

    int B  = in_sizes[0] / 2;   // rows
    int n8 = B / 8;
    int rem_start = n8 * 8;

    if (n8 > 0) {
        int threads = 256;
        int blocks  = (n8 + threads - 1) / threads;
        net24_vec8_kernel<<<blocks, threads>>>(
            (const float4*)x, (float4*)out,
            fc1_tw, fc1_power, fc1_bias, m4_tw, m4_power, m4_bias3, n8);
    }
    if (rem_start < B) {
        int rem = B - rem_start;
        net24_tail_kernel<<<(rem + 127) / 128, 128>>>(
            (const float2*)x, out,
            fc1_tw, fc1_power, fc1_bias, m4_tw, m4_power, m4_bias3,
            rem_start, B);
    }
}